// round 1
// baseline (speedup 1.0000x reference)
#include <cuda_runtime.h>
#include <math.h>

#define B_    256
#define S_    300
#define D_    64
#define DFF_  256
#define NTOK  (B_*S_)        // 76800

// ---------------- scratch (__device__ globals: allocation-guard safe) -------
__device__ __align__(16) float g_q [(size_t)NTOK*D_];
__device__ __align__(16) float g_k [(size_t)NTOK*D_];
__device__ __align__(16) float g_v [(size_t)NTOK*D_];
__device__ __align__(16) float g_z1[(size_t)NTOK*D_];

__device__ __align__(16) float g_WE[64*192];     // packed Wq|Wk|Wv  [k][c]
__device__ __align__(16) float g_WH[256*192];    // packed Wcq|Wck|Wcv
__device__ float g_bE[192], g_gE[192], g_betaE[192];
__device__ float g_bH[192], g_gH[192], g_betaH[192];

// ---------------- K0: pack weights / params --------------------------------
__global__ void pack_kernel(
    const float* __restrict__ Wq,  const float* __restrict__ bq,
    const float* __restrict__ Wk,  const float* __restrict__ bk,
    const float* __restrict__ Wv,  const float* __restrict__ bv,
    const float* __restrict__ Wcq, const float* __restrict__ bcq,
    const float* __restrict__ Wck, const float* __restrict__ bck,
    const float* __restrict__ Wcv, const float* __restrict__ bcv,
    const float* __restrict__ gQE, const float* __restrict__ betaQE,
    const float* __restrict__ gKE, const float* __restrict__ betaKE,
    const float* __restrict__ gVE, const float* __restrict__ betaVE,
    const float* __restrict__ gQH, const float* __restrict__ betaQH,
    const float* __restrict__ gKH, const float* __restrict__ betaKH,
    const float* __restrict__ gVH, const float* __restrict__ betaVH)
{
    const int tid = blockIdx.x * blockDim.x + threadIdx.x;
    const int stride = gridDim.x * blockDim.x;
    for (int idx = tid; idx < 64*192; idx += stride) {
        int k = idx / 192, c = idx % 192, br = c >> 6, j = c & 63;
        const float* W = (br == 0) ? Wq : (br == 1) ? Wk : Wv;
        g_WE[k*192 + c] = W[k*64 + j];
    }
    for (int idx = tid; idx < 256*192; idx += stride) {
        int k = idx / 192, c = idx % 192, br = c >> 6, j = c & 63;
        const float* W = (br == 0) ? Wcq : (br == 1) ? Wck : Wcv;
        g_WH[k*192 + c] = W[k*64 + j];
    }
    for (int c = tid; c < 192; c += stride) {
        int br = c >> 6, j = c & 63;
        g_bE[c]    = ((br==0)?bq    :(br==1)?bk    :bv    )[j];
        g_bH[c]    = ((br==0)?bcq   :(br==1)?bck   :bcv   )[j];
        g_gE[c]    = ((br==0)?gQE   :(br==1)?gKE   :gVE   )[j];
        g_betaE[c] = ((br==0)?betaQE:(br==1)?betaKE:betaVE)[j];
        g_gH[c]    = ((br==0)?gQH   :(br==1)?gKH   :gVH   )[j];
        g_betaH[c] = ((br==0)?betaQH:(br==1)?betaKH:betaVH)[j];
    }
}

// ---------------- K1: gated projections (E*H) -> q,k,v ---------------------
// 32 tokens per block, 256 threads: thread (tg=tid/32, cg=tid%32) computes
// 4 tokens x 6 cols (cols c = cg + 32*i). LN per (token, branch) via warp shfl.
__global__ __launch_bounds__(256, 2)
void proj_kernel(const float* __restrict__ state, const float* __restrict__ Hin)
{
    __shared__ __align__(16) float Xs[32*64];
    __shared__ __align__(16) float Hs[32*256];
    const int tid = threadIdx.x;
    const size_t tok0 = (size_t)blockIdx.x * 32;

    {
        const float4* sx = (const float4*)(state + tok0*64);
        float4* dx = (float4*)Xs;
        #pragma unroll
        for (int i = 0; i < 2; i++) dx[tid + 256*i] = sx[tid + 256*i];
        const float4* sh = (const float4*)(Hin + tok0*256);
        float4* dh = (float4*)Hs;
        #pragma unroll
        for (int i = 0; i < 8; i++) dh[tid + 256*i] = sh[tid + 256*i];
    }
    __syncthreads();

    const int tg = tid >> 5, cg = tid & 31;
    const float* xrow = Xs + tg*4*64;
    const float* hrow = Hs + tg*4*256;

    float accE[4][6], accH[4][6];
    #pragma unroll
    for (int t = 0; t < 4; t++)
        #pragma unroll
        for (int i = 0; i < 6; i++) { accE[t][i] = 0.f; accH[t][i] = 0.f; }

    #pragma unroll 4
    for (int k = 0; k < 64; k++) {
        float w[6];
        #pragma unroll
        for (int i = 0; i < 6; i++) w[i] = g_WE[k*192 + cg + 32*i];
        #pragma unroll
        for (int t = 0; t < 4; t++) {
            float a = xrow[t*64 + k];
            #pragma unroll
            for (int i = 0; i < 6; i++) accE[t][i] = fmaf(a, w[i], accE[t][i]);
        }
    }
    #pragma unroll 4
    for (int k = 0; k < 256; k++) {
        float w[6];
        #pragma unroll
        for (int i = 0; i < 6; i++) w[i] = g_WH[k*192 + cg + 32*i];
        #pragma unroll
        for (int t = 0; t < 4; t++) {
            float a = hrow[t*256 + k];
            #pragma unroll
            for (int i = 0; i < 6; i++) accH[t][i] = fmaf(a, w[i], accH[t][i]);
        }
    }
    #pragma unroll
    for (int i = 0; i < 6; i++) {
        float be = g_bE[cg + 32*i], bh = g_bH[cg + 32*i];
        #pragma unroll
        for (int t = 0; t < 4; t++) { accE[t][i] += be; accH[t][i] += bh; }
    }

    #pragma unroll
    for (int t = 0; t < 4; t++) {
        const size_t tok = tok0 + tg*4 + t;
        #pragma unroll
        for (int br = 0; br < 3; br++) {
            float e0 = accE[t][2*br], e1 = accE[t][2*br+1];
            float h0 = accH[t][2*br], h1 = accH[t][2*br+1];
            float s1 = e0 + e1, s2 = fmaf(e0, e0, e1*e1);
            float s3 = h0 + h1, s4 = fmaf(h0, h0, h1*h1);
            #pragma unroll
            for (int off = 16; off > 0; off >>= 1) {
                s1 += __shfl_xor_sync(0xffffffffu, s1, off);
                s2 += __shfl_xor_sync(0xffffffffu, s2, off);
                s3 += __shfl_xor_sync(0xffffffffu, s3, off);
                s4 += __shfl_xor_sync(0xffffffffu, s4, off);
            }
            float mE = s1 * (1.f/64.f), mH = s3 * (1.f/64.f);
            float rE = rsqrtf(s2*(1.f/64.f) - mE*mE + 1e-5f);
            float rH = rsqrtf(s4*(1.f/64.f) - mH*mH + 1e-5f);
            int c0 = cg + 64*br, c1 = c0 + 32;
            float o0 = ((e0-mE)*rE*g_gE[c0] + g_betaE[c0]) *
                       ((h0-mH)*rH*g_gH[c0] + g_betaH[c0]);
            float o1 = ((e1-mE)*rE*g_gE[c1] + g_betaE[c1]) *
                       ((h1-mH)*rH*g_gH[c1] + g_betaH[c1]);
            float* dst = (br == 0) ? g_q : (br == 1) ? g_k : g_v;
            dst[tok*64 + cg]      = o0;
            dst[tok*64 + cg + 32] = o1;
        }
    }
}

// ---------------- K2: attention + residual -> Z1 ---------------------------
// One block per (b,h). Thread = one query row. K/V staged in smem in 150-row
// chunks. Scores are ~unit-variance (LN'd gated inputs, /sqrt(32)) so exp()
// without running-max is numerically safe; saves 32 FMA/key of rescaling.
#define ACH 150
__global__ __launch_bounds__(320, 2)
void attn_kernel(const float* __restrict__ state)
{
    __shared__ __align__(16) float4 Ks[ACH*8];
    __shared__ __align__(16) float4 Vs[ACH*8];
    const int tid = threadIdx.x;
    const int b = blockIdx.x >> 1, h = blockIdx.x & 1;
    const size_t base = (size_t)b * S_ * 64 + h * 32;

    float4 qv[8];
    float acc[32];
    float l = 0.f;
    const bool active = (tid < S_);
    if (active) {
        const float4* qp = (const float4*)(g_q + base + (size_t)tid*64);
        const float sc = 0.17677669529663687f;   // 1/sqrt(32)
        #pragma unroll
        for (int j = 0; j < 8; j++) {
            float4 v = qp[j];
            v.x *= sc; v.y *= sc; v.z *= sc; v.w *= sc;
            qv[j] = v;
        }
        #pragma unroll
        for (int d = 0; d < 32; d++) acc[d] = 0.f;
    }

    for (int c0 = 0; c0 < S_; c0 += ACH) {
        __syncthreads();
        for (int idx = tid; idx < ACH*8; idx += 320) {
            int kk = idx >> 3, j = idx & 7;
            size_t g = base + (size_t)(c0 + kk)*64;
            Ks[idx] = ((const float4*)(g_k + g))[j];
            Vs[idx] = ((const float4*)(g_v + g))[j];
        }
        __syncthreads();
        if (active) {
            for (int kk = 0; kk < ACH; kk++) {
                const float4* kr = &Ks[kk*8];
                float dx = 0.f, dy = 0.f, dz = 0.f, dw = 0.f;
                #pragma unroll
                for (int j = 0; j < 8; j++) {
                    float4 k4 = kr[j];
                    dx = fmaf(qv[j].x, k4.x, dx);
                    dy = fmaf(qv[j].y, k4.y, dy);
                    dz = fmaf(qv[j].z, k4.z, dz);
                    dw = fmaf(qv[j].w, k4.w, dw);
                }
                float p = __expf((dx + dy) + (dz + dw));
                l += p;
                const float4* vr = &Vs[kk*8];
                #pragma unroll
                for (int j = 0; j < 8; j++) {
                    float4 v4 = vr[j];
                    acc[4*j+0] = fmaf(p, v4.x, acc[4*j+0]);
                    acc[4*j+1] = fmaf(p, v4.y, acc[4*j+1]);
                    acc[4*j+2] = fmaf(p, v4.z, acc[4*j+2]);
                    acc[4*j+3] = fmaf(p, v4.w, acc[4*j+3]);
                }
            }
        }
    }

    if (active) {
        float inv = 1.0f / l;
        const float4* sp = (const float4*)(state + base + (size_t)tid*64);
        float4* zp = (float4*)(g_z1 + base + (size_t)tid*64);
        #pragma unroll
        for (int j = 0; j < 8; j++) {
            float4 sv = sp[j]; float4 o;
            o.x = fmaf(acc[4*j+0], inv, sv.x);
            o.y = fmaf(acc[4*j+1], inv, sv.y);
            o.z = fmaf(acc[4*j+2], inv, sv.z);
            o.w = fmaf(acc[4*j+3], inv, sv.w);
            zp[j] = o;
        }
    }
}

// ---------------- K3: LN -> FFN(gelu) -> +Z1 -> out -------------------------
__global__ __launch_bounds__(256, 2)
void ffn_kernel(const float* __restrict__ W1, const float* __restrict__ b1,
                const float* __restrict__ W2, const float* __restrict__ b2,
                const float* __restrict__ g1, const float* __restrict__ beta1,
                float* __restrict__ out)
{
    __shared__ __align__(16) float z1s[32*64];   // z1 tile, LN'd in place
    __shared__ __align__(16) float h3s[32*256];  // gelu(z2@W1+b1)
    const int tid = threadIdx.x;
    const size_t tok0 = (size_t)blockIdx.x * 32;

    {
        const float4* sz = (const float4*)(g_z1 + tok0*64);
        float4* dz = (float4*)z1s;
        #pragma unroll
        for (int i = 0; i < 2; i++) dz[tid + 256*i] = sz[tid + 256*i];
    }
    __syncthreads();

    const int tg = tid >> 5, cg = tid & 31;

    // stash residual values this thread will need at the end (before in-place LN)
    float rz[4][2];
    #pragma unroll
    for (int t = 0; t < 4; t++)
        #pragma unroll
        for (int i = 0; i < 2; i++)
            rz[t][i] = z1s[(tg*4 + t)*64 + cg + 32*i];

    // LayerNorm: warp wp handles tokens wp*4..wp*4+3; 8 lanes per token.
    const int lane = tid & 31;
    const int t0   = tg*4 + (lane >> 3);
    const int segc = (lane & 7) * 8;
    float vals[8]; float s1 = 0.f, s2 = 0.f;
    #pragma unroll
    for (int u = 0; u < 8; u++) {
        float x = z1s[t0*64 + segc + u];
        vals[u] = x; s1 += x; s2 = fmaf(x, x, s2);
    }
    #pragma unroll
    for (int off = 4; off > 0; off >>= 1) {
        s1 += __shfl_xor_sync(0xffffffffu, s1, off);
        s2 += __shfl_xor_sync(0xffffffffu, s2, off);
    }
    float m = s1 * (1.f/64.f);
    float r = rsqrtf(s2*(1.f/64.f) - m*m + 1e-5f);
    __syncthreads();
    #pragma unroll
    for (int u = 0; u < 8; u++) {
        int c = segc + u;
        z1s[t0*64 + c] = (vals[u] - m)*r*g1[c] + beta1[c];
    }
    __syncthreads();

    // GEMM1: [32,64] @ W1[64,256], exact-erf GELU
    float acc1[4][8];
    #pragma unroll
    for (int t = 0; t < 4; t++)
        #pragma unroll
        for (int i = 0; i < 8; i++) acc1[t][i] = 0.f;
    #pragma unroll 4
    for (int k = 0; k < 64; k++) {
        float w[8];
        #pragma unroll
        for (int i = 0; i < 8; i++) w[i] = W1[k*256 + cg + 32*i];
        #pragma unroll
        for (int t = 0; t < 4; t++) {
            float a = z1s[(tg*4 + t)*64 + k];
            #pragma unroll
            for (int i = 0; i < 8; i++) acc1[t][i] = fmaf(a, w[i], acc1[t][i]);
        }
    }
    #pragma unroll
    for (int i = 0; i < 8; i++) {
        int c = cg + 32*i;
        float bb = b1[c];
        #pragma unroll
        for (int t = 0; t < 4; t++) {
            float x = acc1[t][i] + bb;
            float gl = 0.5f * x * (1.f + erff(x * 0.70710678118654752f));
            h3s[(tg*4 + t)*256 + c] = gl;
        }
    }
    __syncthreads();

    // GEMM2: [32,256] @ W2[256,64] + residual
    float acc2[4][2];
    #pragma unroll
    for (int t = 0; t < 4; t++) { acc2[t][0] = 0.f; acc2[t][1] = 0.f; }
    #pragma unroll 4
    for (int k = 0; k < 256; k++) {
        float w0 = W2[k*64 + cg], w1 = W2[k*64 + cg + 32];
        #pragma unroll
        for (int t = 0; t < 4; t++) {
            float a = h3s[(tg*4 + t)*256 + k];
            acc2[t][0] = fmaf(a, w0, acc2[t][0]);
            acc2[t][1] = fmaf(a, w1, acc2[t][1]);
        }
    }
    #pragma unroll
    for (int i = 0; i < 2; i++) {
        int c = cg + 32*i;
        float bb = b2[c];
        #pragma unroll
        for (int t = 0; t < 4; t++)
            out[(tok0 + tg*4 + t)*64 + c] = rz[t][i] + acc2[t][i] + bb;
    }
}

// ---------------- launcher --------------------------------------------------
extern "C" void kernel_launch(void* const* d_in, const int* in_sizes, int n_in,
                              void* d_out, int out_size)
{
    const float* state  = (const float*)d_in[0];
    const float* H      = (const float*)d_in[1];
    const float* Wq     = (const float*)d_in[2];
    const float* bq     = (const float*)d_in[3];
    const float* Wk     = (const float*)d_in[4];
    const float* bk     = (const float*)d_in[5];
    const float* Wv     = (const float*)d_in[6];
    const float* bv     = (const float*)d_in[7];
    const float* Wcq    = (const float*)d_in[8];
    const float* bcq    = (const float*)d_in[9];
    const float* Wck    = (const float*)d_in[10];
    const float* bck    = (const float*)d_in[11];
    const float* Wcv    = (const float*)d_in[12];
    const float* bcv    = (const float*)d_in[13];
    const float* gQE    = (const float*)d_in[14];
    const float* betaQE = (const float*)d_in[15];
    const float* gKE    = (const float*)d_in[16];
    const float* betaKE = (const float*)d_in[17];
    const float* gVE    = (const float*)d_in[18];
    const float* betaVE = (const float*)d_in[19];
    const float* gQH    = (const float*)d_in[20];
    const float* betaQH = (const float*)d_in[21];
    const float* gKH    = (const float*)d_in[22];
    const float* betaKH = (const float*)d_in[23];
    const float* gVH    = (const float*)d_in[24];
    const float* betaVH = (const float*)d_in[25];
    const float* W1     = (const float*)d_in[26];
    const float* b1     = (const float*)d_in[27];
    const float* W2     = (const float*)d_in[28];
    const float* b2     = (const float*)d_in[29];
    const float* g1     = (const float*)d_in[30];
    const float* beta1  = (const float*)d_in[31];
    float* out = (float*)d_out;

    pack_kernel<<<96, 256>>>(Wq, bq, Wk, bk, Wv, bv,
                             Wcq, bcq, Wck, bck, Wcv, bcv,
                             gQE, betaQE, gKE, betaKE, gVE, betaVE,
                             gQH, betaQH, gKH, betaKH, gVH, betaVH);
    proj_kernel<<<NTOK/32, 256>>>(state, H);
    attn_kernel<<<B_*2, 320>>>(state);
    ffn_kernel<<<NTOK/32, 256>>>(W1, b1, W2, b2, g1, beta1, out);
}

// round 3
// speedup vs baseline: 1.5352x; 1.5352x over previous
#include <cuda_runtime.h>
#include <cuda_fp16.h>
#include <cstdint>
#include <stdint.h>
#include <math.h>

#define B_    256
#define S_    300
#define NTOK  (B_*S_)        // 76800

// ---------------- scratch (__device__ globals) ------------------------------
__device__ __align__(16) float g_q [(size_t)NTOK*64];
__device__ __align__(16) float g_k [(size_t)NTOK*64];
__device__ __align__(16) float g_v [(size_t)NTOK*64];
__device__ __align__(16) float g_z1[(size_t)NTOK*64];

// fragment-order fp16 weight streams: [ntile][lane][kstep][{b0,b1}] (half2 units)
__device__ __align__(16) __half2 g_WEf[24*32*4*2];    // 192 cols, K=64
__device__ __align__(16) __half2 g_WHf[24*32*16*2];   // 192 cols, K=256
__device__ __align__(16) __half2 g_W1f[32*32*4*2];    // 256 cols, K=64
__device__ __align__(16) __half2 g_W2f[ 8*32*16*2];   // 64 cols,  K=256

__device__ float g_bE[192], g_gE[192], g_betaE[192];
__device__ float g_bH[192], g_gH[192], g_betaH[192];

// ---------------- mma / ldmatrix helpers ------------------------------------
__device__ __forceinline__ void mma_f16(float* d, const unsigned int* a,
                                        unsigned int b0, unsigned int b1) {
    asm volatile(
        "mma.sync.aligned.m16n8k16.row.col.f32.f16.f16.f32 "
        "{%0,%1,%2,%3}, {%4,%5,%6,%7}, {%8,%9}, {%0,%1,%2,%3};\n"
        : "+f"(d[0]), "+f"(d[1]), "+f"(d[2]), "+f"(d[3])
        : "r"(a[0]), "r"(a[1]), "r"(a[2]), "r"(a[3]), "r"(b0), "r"(b1));
}
__device__ __forceinline__ void ldsm4(unsigned int* a, const void* p) {
    unsigned int s = (unsigned int)__cvta_generic_to_shared(p);
    asm volatile("ldmatrix.sync.aligned.m8n8.x4.shared.b16 {%0,%1,%2,%3}, [%4];\n"
        : "=r"(a[0]), "=r"(a[1]), "=r"(a[2]), "=r"(a[3]) : "r"(s));
}

// ---------------- K0: pack weights into fragment streams --------------------
__global__ void pack_kernel(
    const float* __restrict__ Wq,  const float* __restrict__ bq,
    const float* __restrict__ Wk,  const float* __restrict__ bk,
    const float* __restrict__ Wv,  const float* __restrict__ bv,
    const float* __restrict__ Wcq, const float* __restrict__ bcq,
    const float* __restrict__ Wck, const float* __restrict__ bck,
    const float* __restrict__ Wcv, const float* __restrict__ bcv,
    const float* __restrict__ gQE, const float* __restrict__ betaQE,
    const float* __restrict__ gKE, const float* __restrict__ betaKE,
    const float* __restrict__ gVE, const float* __restrict__ betaVE,
    const float* __restrict__ gQH, const float* __restrict__ betaQH,
    const float* __restrict__ gKH, const float* __restrict__ betaKH,
    const float* __restrict__ gVH, const float* __restrict__ betaVH,
    const float* __restrict__ W1,  const float* __restrict__ W2)
{
    const int tid0 = blockIdx.x * blockDim.x + threadIdx.x;
    const int stride = gridDim.x * blockDim.x;

    // WE: cols 0..191 over {Wq|Wk|Wv}[64][64], K=64 (4 ksteps)
    for (int idx = tid0; idx < 24*32*4*2; idx += stride) {
        int j = idx & 1, ks = (idx >> 1) & 3, l = (idx >> 3) & 31, nt = idx >> 8;
        int g = l >> 2, t = l & 3;
        int c = nt*8 + g;
        int k = ks*16 + 2*t + j*8;
        int br = c >> 6, cc = c & 63;
        const float* W = (br == 0) ? Wq : (br == 1) ? Wk : Wv;
        g_WEf[idx] = __floats2half2_rn(W[k*64 + cc], W[(k+1)*64 + cc]);
    }
    // WH: cols 0..191 over {Wcq|Wck|Wcv}[256][64], K=256 (16 ksteps)
    for (int idx = tid0; idx < 24*32*16*2; idx += stride) {
        int j = idx & 1, ks = (idx >> 1) & 15, l = (idx >> 5) & 31, nt = idx >> 10;
        int g = l >> 2, t = l & 3;
        int c = nt*8 + g;
        int k = ks*16 + 2*t + j*8;
        int br = c >> 6, cc = c & 63;
        const float* W = (br == 0) ? Wcq : (br == 1) ? Wck : Wcv;
        g_WHf[idx] = __floats2half2_rn(W[k*64 + cc], W[(k+1)*64 + cc]);
    }
    // W1[64][256], K=64
    for (int idx = tid0; idx < 32*32*4*2; idx += stride) {
        int j = idx & 1, ks = (idx >> 1) & 3, l = (idx >> 3) & 31, nt = idx >> 8;
        int g = l >> 2, t = l & 3;
        int c = nt*8 + g;
        int k = ks*16 + 2*t + j*8;
        g_W1f[idx] = __floats2half2_rn(W1[k*256 + c], W1[(k+1)*256 + c]);
    }
    // W2[256][64], K=256
    for (int idx = tid0; idx < 8*32*16*2; idx += stride) {
        int j = idx & 1, ks = (idx >> 1) & 15, l = (idx >> 5) & 31, nt = idx >> 10;
        int g = l >> 2, t = l & 3;
        int c = nt*8 + g;
        int k = ks*16 + 2*t + j*8;
        g_W2f[idx] = __floats2half2_rn(W2[k*64 + c], W2[(k+1)*64 + c]);
    }
    for (int c = tid0; c < 192; c += stride) {
        int br = c >> 6, j = c & 63;
        g_bE[c]    = ((br==0)?bq    :(br==1)?bk    :bv    )[j];
        g_bH[c]    = ((br==0)?bcq   :(br==1)?bck   :bcv   )[j];
        g_gE[c]    = ((br==0)?gQE   :(br==1)?gKE   :gVE   )[j];
        g_betaE[c] = ((br==0)?betaQE:(br==1)?betaKE:betaVE)[j];
        g_gH[c]    = ((br==0)?gQH   :(br==1)?gKH   :gVH   )[j];
        g_betaH[c] = ((br==0)?betaQH:(br==1)?betaKH:betaVH)[j];
    }
}

// ---------------- K1: gated projections via mma -----------------------------
// 16 tokens/block, 256 threads (8 warps). Warp w: 24 cols (3 n8-tiles) at w*24.
#define XR 72
#define HR 264
#define ER 196
__global__ __launch_bounds__(256)
void proj_kernel(const float* __restrict__ state, const float* __restrict__ Hin)
{
    __shared__ __align__(16) __half Xs[16*XR];
    __shared__ __align__(16) __half Hs[16*HR];
    __shared__ __align__(16) float  Ef[16*ER];
    __shared__ __align__(16) float  Hf[16*ER];
    const int tid = threadIdx.x;
    const size_t tok0 = (size_t)blockIdx.x * 16;

    // stage inputs as fp16 (padded strides -> conflict-free ldmatrix)
    {
        int idx = tid * 4;                       // covers 16*64
        int r = idx >> 6, c = idx & 63;
        float4 f = *(const float4*)(state + (tok0 + r)*64 + c);
        *(__half2*)(Xs + r*XR + c)     = __floats2half2_rn(f.x, f.y);
        *(__half2*)(Xs + r*XR + c + 2) = __floats2half2_rn(f.z, f.w);
        #pragma unroll
        for (int it = 0; it < 4; it++) {
            int j2 = (tid + 256*it) * 4;          // covers 16*256
            int rh = j2 >> 8, ch = j2 & 255;
            float4 fh = *(const float4*)(Hin + (tok0 + rh)*256 + ch);
            *(__half2*)(Hs + rh*HR + ch)     = __floats2half2_rn(fh.x, fh.y);
            *(__half2*)(Hs + rh*HR + ch + 2) = __floats2half2_rn(fh.z, fh.w);
        }
    }
    __syncthreads();

    const int w = tid >> 5, l = tid & 31;
    const int g = l >> 2, t = l & 3;
    const int ldrow = (l & 15), ldcol = (l >> 4) * 8;

    // ---- E = state @ WE  (K=64) ----
    float accE[3][4];
    #pragma unroll
    for (int nt = 0; nt < 3; nt++)
        #pragma unroll
        for (int i = 0; i < 4; i++) accE[nt][i] = 0.f;
    #pragma unroll
    for (int ksp = 0; ksp < 2; ksp++) {
        unsigned int a[8];
        ldsm4(a,     Xs + ldrow*XR + ksp*32 + ldcol);
        ldsm4(a + 4, Xs + ldrow*XR + ksp*32 + 16 + ldcol);
        #pragma unroll
        for (int nt = 0; nt < 3; nt++) {
            const uint4 bfrag = *(const uint4*)&g_WEf[(((w*3 + nt)*32 + l)*4 + ksp*2)*2];
            mma_f16(accE[nt], a,     bfrag.x, bfrag.y);
            mma_f16(accE[nt], a + 4, bfrag.z, bfrag.w);
        }
    }
    #pragma unroll
    for (int nt = 0; nt < 3; nt++) {
        int c0 = w*24 + nt*8 + 2*t;
        Ef[g*ER + c0]       = accE[nt][0];
        Ef[g*ER + c0 + 1]   = accE[nt][1];
        Ef[(g+8)*ER + c0]   = accE[nt][2];
        Ef[(g+8)*ER + c0+1] = accE[nt][3];
    }

    // ---- Hh = H @ WH  (K=256) ----
    float accH[3][4];
    #pragma unroll
    for (int nt = 0; nt < 3; nt++)
        #pragma unroll
        for (int i = 0; i < 4; i++) accH[nt][i] = 0.f;
    #pragma unroll
    for (int ksp = 0; ksp < 8; ksp++) {
        unsigned int a[8];
        ldsm4(a,     Hs + ldrow*HR + ksp*32 + ldcol);
        ldsm4(a + 4, Hs + ldrow*HR + ksp*32 + 16 + ldcol);
        #pragma unroll
        for (int nt = 0; nt < 3; nt++) {
            const uint4 bfrag = *(const uint4*)&g_WHf[(((w*3 + nt)*32 + l)*16 + ksp*2)*2];
            mma_f16(accH[nt], a,     bfrag.x, bfrag.y);
            mma_f16(accH[nt], a + 4, bfrag.z, bfrag.w);
        }
    }
    #pragma unroll
    for (int nt = 0; nt < 3; nt++) {
        int c0 = w*24 + nt*8 + 2*t;
        Hf[g*ER + c0]       = accH[nt][0];
        Hf[g*ER + c0 + 1]   = accH[nt][1];
        Hf[(g+8)*ER + c0]   = accH[nt][2];
        Hf[(g+8)*ER + c0+1] = accH[nt][3];
    }
    __syncthreads();

    // ---- LN(E)+LN(H), gate, write q/k/v -------------------------------------
    // 192 workers: (token, branch, 16-col quarter); 4-lane shfl groups.
    if (tid < 192) {
        int tok = tid / 12, sub = tid % 12;
        int br = sub >> 2, qtr = sub & 3;
        int cb = br*64 + qtr*16;
        float e[16], h[16];
        float s1 = 0.f, s2 = 0.f, s3 = 0.f, s4 = 0.f;
        #pragma unroll
        for (int u = 0; u < 16; u++) {
            int c = cb + u;
            float ev = Ef[tok*ER + c] + g_bE[c];
            float hv = Hf[tok*ER + c] + g_bH[c];
            e[u] = ev; h[u] = hv;
            s1 += ev; s2 = fmaf(ev, ev, s2);
            s3 += hv; s4 = fmaf(hv, hv, s4);
        }
        #pragma unroll
        for (int off = 1; off <= 2; off <<= 1) {
            s1 += __shfl_xor_sync(0xffffffffu, s1, off);
            s2 += __shfl_xor_sync(0xffffffffu, s2, off);
            s3 += __shfl_xor_sync(0xffffffffu, s3, off);
            s4 += __shfl_xor_sync(0xffffffffu, s4, off);
        }
        float mE = s1 * (1.f/64.f), mH = s3 * (1.f/64.f);
        float rE = rsqrtf(s2*(1.f/64.f) - mE*mE + 1e-5f);
        float rH = rsqrtf(s4*(1.f/64.f) - mH*mH + 1e-5f);
        float* dst = (br == 0) ? g_q : (br == 1) ? g_k : g_v;
        size_t base = (tok0 + tok)*64 + qtr*16;
        #pragma unroll
        for (int u = 0; u < 16; u++) {
            int c = cb + u;
            dst[base + u] = ((e[u]-mE)*rE*g_gE[c] + g_betaE[c]) *
                            ((h[u]-mH)*rH*g_gH[c] + g_betaH[c]);
        }
    }
}

// ---------------- K2: attention + residual -> Z1 (fp32) ---------------------
#define ACH 150
__global__ __launch_bounds__(320, 2)
void attn_kernel(const float* __restrict__ state)
{
    __shared__ __align__(16) float4 Ks[ACH*8];
    __shared__ __align__(16) float4 Vs[ACH*8];
    const int tid = threadIdx.x;
    const int b = blockIdx.x >> 1, h = blockIdx.x & 1;
    const size_t base = (size_t)b * S_ * 64 + h * 32;

    float4 qv[8];
    float acc[32];
    float l = 0.f;
    const bool active = (tid < S_);
    if (active) {
        const float4* qp = (const float4*)(g_q + base + (size_t)tid*64);
        const float sc = 0.17677669529663687f;   // 1/sqrt(32)
        #pragma unroll
        for (int j = 0; j < 8; j++) {
            float4 v = qp[j];
            v.x *= sc; v.y *= sc; v.z *= sc; v.w *= sc;
            qv[j] = v;
        }
        #pragma unroll
        for (int d = 0; d < 32; d++) acc[d] = 0.f;
    }

    for (int c0 = 0; c0 < S_; c0 += ACH) {
        __syncthreads();
        for (int idx = tid; idx < ACH*8; idx += 320) {
            int kk = idx >> 3, j = idx & 7;
            size_t g = base + (size_t)(c0 + kk)*64;
            Ks[idx] = ((const float4*)(g_k + g))[j];
            Vs[idx] = ((const float4*)(g_v + g))[j];
        }
        __syncthreads();
        if (active) {
            for (int kk = 0; kk < ACH; kk++) {
                const float4* kr = &Ks[kk*8];
                float dx = 0.f, dy = 0.f, dz = 0.f, dw = 0.f;
                #pragma unroll
                for (int j = 0; j < 8; j++) {
                    float4 k4 = kr[j];
                    dx = fmaf(qv[j].x, k4.x, dx);
                    dy = fmaf(qv[j].y, k4.y, dy);
                    dz = fmaf(qv[j].z, k4.z, dz);
                    dw = fmaf(qv[j].w, k4.w, dw);
                }
                float p = __expf((dx + dy) + (dz + dw));
                l += p;
                const float4* vr = &Vs[kk*8];
                #pragma unroll
                for (int j = 0; j < 8; j++) {
                    float4 v4 = vr[j];
                    acc[4*j+0] = fmaf(p, v4.x, acc[4*j+0]);
                    acc[4*j+1] = fmaf(p, v4.y, acc[4*j+1]);
                    acc[4*j+2] = fmaf(p, v4.z, acc[4*j+2]);
                    acc[4*j+3] = fmaf(p, v4.w, acc[4*j+3]);
                }
            }
        }
    }

    if (active) {
        float inv = 1.0f / l;
        const float4* sp = (const float4*)(state + base + (size_t)tid*64);
        float4* zp = (float4*)(g_z1 + base + (size_t)tid*64);
        #pragma unroll
        for (int j = 0; j < 8; j++) {
            float4 sv = sp[j]; float4 o;
            o.x = fmaf(acc[4*j+0], inv, sv.x);
            o.y = fmaf(acc[4*j+1], inv, sv.y);
            o.z = fmaf(acc[4*j+2], inv, sv.z);
            o.w = fmaf(acc[4*j+3], inv, sv.w);
            zp[j] = o;
        }
    }
}

// ---------------- K3: LN -> FFN(gelu) -> +Z1 via mma ------------------------
// 32 tokens/block, 256 threads (8 warps).
#define ZR  72
#define H3R 264
#define Z1R 68
__global__ __launch_bounds__(256)
void ffn_kernel(const float* __restrict__ b1, const float* __restrict__ b2,
                const float* __restrict__ g1, const float* __restrict__ beta1,
                float* __restrict__ out)
{
    __shared__ __align__(16) __half Z2s[32*ZR];
    __shared__ __align__(16) __half H3s[32*H3R];
    __shared__ __align__(16) float  Z1s[32*Z1R];
    const int tid = threadIdx.x;
    const size_t tok0 = (size_t)blockIdx.x * 32;

    // ---- Phase 1: LN(z1) -> fp16, stash z1 fp32 -----------------------------
    {
        int tk = tid >> 3, sg = tid & 7;         // 8 floats per thread
        const float* src = g_z1 + (tok0 + tk)*64 + sg*8;
        float4 f0 = *(const float4*)src;
        float4 f1 = *(const float4*)(src + 4);
        float v[8] = {f0.x, f0.y, f0.z, f0.w, f1.x, f1.y, f1.z, f1.w};
        float s1 = 0.f, s2 = 0.f;
        #pragma unroll
        for (int u = 0; u < 8; u++) { s1 += v[u]; s2 = fmaf(v[u], v[u], s2); }
        #pragma unroll
        for (int off = 1; off <= 4; off <<= 1) {
            s1 += __shfl_xor_sync(0xffffffffu, s1, off);
            s2 += __shfl_xor_sync(0xffffffffu, s2, off);
        }
        float m = s1 * (1.f/64.f);
        float r = rsqrtf(s2*(1.f/64.f) - m*m + 1e-5f);
        *(float4*)(Z1s + tk*Z1R + sg*8)     = f0;
        *(float4*)(Z1s + tk*Z1R + sg*8 + 4) = f1;
        #pragma unroll
        for (int u = 0; u < 8; u += 2) {
            int c = sg*8 + u;
            float a0 = (v[u]   - m)*r*g1[c]   + beta1[c];
            float a1 = (v[u+1] - m)*r*g1[c+1] + beta1[c+1];
            *(__half2*)(Z2s + tk*ZR + c) = __floats2half2_rn(a0, a1);
        }
    }
    __syncthreads();

    const int w = tid >> 5, l = tid & 31;
    const int g = l >> 2, t = l & 3;
    const int ldrow = (l & 15), ldcol = (l >> 4) * 8;
    const int mt = w & 1;

    // ---- GEMM1: [32,64]@W1 -> [32,256], exact GELU --------------------------
    {
        const int cq = w >> 1;                    // col quarter (64 cols)
        float acc1[8][4];
        #pragma unroll
        for (int nt = 0; nt < 8; nt++)
            #pragma unroll
            for (int i = 0; i < 4; i++) acc1[nt][i] = 0.f;
        #pragma unroll
        for (int ksp = 0; ksp < 2; ksp++) {
            unsigned int a[8];
            ldsm4(a,     Z2s + (mt*16 + ldrow)*ZR + ksp*32 + ldcol);
            ldsm4(a + 4, Z2s + (mt*16 + ldrow)*ZR + ksp*32 + 16 + ldcol);
            #pragma unroll
            for (int nt = 0; nt < 8; nt++) {
                const uint4 bfrag = *(const uint4*)&g_W1f[(((cq*8 + nt)*32 + l)*4 + ksp*2)*2];
                mma_f16(acc1[nt], a,     bfrag.x, bfrag.y);
                mma_f16(acc1[nt], a + 4, bfrag.z, bfrag.w);
            }
        }
        #pragma unroll
        for (int nt = 0; nt < 8; nt++) {
            int c0 = cq*64 + nt*8 + 2*t;
            float bb0 = b1[c0], bb1 = b1[c0 + 1];
            float x0 = acc1[nt][0] + bb0, x1 = acc1[nt][1] + bb1;
            float x2 = acc1[nt][2] + bb0, x3 = acc1[nt][3] + bb1;
            x0 = 0.5f*x0*(1.f + erff(x0*0.70710678118654752f));
            x1 = 0.5f*x1*(1.f + erff(x1*0.70710678118654752f));
            x2 = 0.5f*x2*(1.f + erff(x2*0.70710678118654752f));
            x3 = 0.5f*x3*(1.f + erff(x3*0.70710678118654752f));
            *(__half2*)(H3s + (mt*16 + g)*H3R + c0)     = __floats2half2_rn(x0, x1);
            *(__half2*)(H3s + (mt*16 + g + 8)*H3R + c0) = __floats2half2_rn(x2, x3);
        }
    }
    __syncthreads();

    // ---- GEMM2: [32,256]@W2 -> [32,64], + b2 + residual ---------------------
    {
        const int np = w >> 1;                    // 16-col slice
        float acc2[2][4];
        #pragma unroll
        for (int nt = 0; nt < 2; nt++)
            #pragma unroll
            for (int i = 0; i < 4; i++) acc2[nt][i] = 0.f;
        #pragma unroll
        for (int ksp = 0; ksp < 8; ksp++) {
            unsigned int a[8];
            ldsm4(a,     H3s + (mt*16 + ldrow)*H3R + ksp*32 + ldcol);
            ldsm4(a + 4, H3s + (mt*16 + ldrow)*H3R + ksp*32 + 16 + ldcol);
            #pragma unroll
            for (int nt = 0; nt < 2; nt++) {
                const uint4 bfrag = *(const uint4*)&g_W2f[(((np*2 + nt)*32 + l)*16 + ksp*2)*2];
                mma_f16(acc2[nt], a,     bfrag.x, bfrag.y);
                mma_f16(acc2[nt], a + 4, bfrag.z, bfrag.w);
            }
        }
        #pragma unroll
        for (int nt = 0; nt < 2; nt++) {
            int c0 = np*16 + nt*8 + 2*t;
            int r0 = mt*16 + g;
            float bb0 = b2[c0], bb1 = b2[c0 + 1];
            out[(tok0 + r0)*64 + c0]       = acc2[nt][0] + bb0 + Z1s[r0*Z1R + c0];
            out[(tok0 + r0)*64 + c0 + 1]   = acc2[nt][1] + bb1 + Z1s[r0*Z1R + c0 + 1];
            out[(tok0 + r0 + 8)*64 + c0]   = acc2[nt][2] + bb0 + Z1s[(r0+8)*Z1R + c0];
            out[(tok0 + r0 + 8)*64 + c0+1] = acc2[nt][3] + bb1 + Z1s[(r0+8)*Z1R + c0 + 1];
        }
    }
}

// ---------------- launcher --------------------------------------------------
extern "C" void kernel_launch(void* const* d_in, const int* in_sizes, int n_in,
                              void* d_out, int out_size)
{
    const float* state  = (const float*)d_in[0];
    const float* H      = (const float*)d_in[1];
    const float* Wq     = (const float*)d_in[2];
    const float* bq     = (const float*)d_in[3];
    const float* Wk     = (const float*)d_in[4];
    const float* bk     = (const float*)d_in[5];
    const float* Wv     = (const float*)d_in[6];
    const float* bv     = (const float*)d_in[7];
    const float* Wcq    = (const float*)d_in[8];
    const float* bcq    = (const float*)d_in[9];
    const float* Wck    = (const float*)d_in[10];
    const float* bck    = (const float*)d_in[11];
    const float* Wcv    = (const float*)d_in[12];
    const float* bcv    = (const float*)d_in[13];
    const float* gQE    = (const float*)d_in[14];
    const float* betaQE = (const float*)d_in[15];
    const float* gKE    = (const float*)d_in[16];
    const float* betaKE = (const float*)d_in[17];
    const float* gVE    = (const float*)d_in[18];
    const float* betaVE = (const float*)d_in[19];
    const float* gQH    = (const float*)d_in[20];
    const float* betaQH = (const float*)d_in[21];
    const float* gKH    = (const float*)d_in[22];
    const float* betaKH = (const float*)d_in[23];
    const float* gVH    = (const float*)d_in[24];
    const float* betaVH = (const float*)d_in[25];
    const float* W1     = (const float*)d_in[26];
    const float* b1     = (const float*)d_in[27];
    const float* W2     = (const float*)d_in[28];
    const float* b2     = (const float*)d_in[29];
    const float* g1     = (const float*)d_in[30];
    const float* beta1  = (const float*)d_in[31];
    float* out = (float*)d_out;

    pack_kernel<<<192, 256>>>(Wq, bq, Wk, bk, Wv, bv,
                              Wcq, bcq, Wck, bck, Wcv, bcv,
                              gQE, betaQE, gKE, betaKE, gVE, betaVE,
                              gQH, betaQH, gKH, betaKH, gVH, betaVH,
                              W1, W2);
    proj_kernel<<<NTOK/16, 256>>>(state, H);
    attn_kernel<<<B_*2, 320>>>(state);
    ffn_kernel<<<NTOK/32, 256>>>(b1, b2, g1, beta1, out);
}

// round 4
// speedup vs baseline: 1.5370x; 1.0012x over previous
#include <cuda_runtime.h>
#include <cuda_fp16.h>
#include <cstdint>
#include <stdint.h>
#include <math.h>

#define B_    256
#define S_    300
#define NTOK  (B_*S_)        // 76800

// ---------------- scratch (__device__ globals) ------------------------------
__device__ __align__(16) float g_q [(size_t)NTOK*64];
__device__ __align__(16) float g_k [(size_t)NTOK*64];
__device__ __align__(16) float g_v [(size_t)NTOK*64];
__device__ __align__(16) float g_z1[(size_t)NTOK*64];

// fragment-order fp16 weight streams: [ntile][lane][kstep][{b0,b1}] (half2 units)
__device__ __align__(16) __half2 g_WEf[24*32*4*2];    // 192 cols, K=64
__device__ __align__(16) __half2 g_WHf[24*32*16*2];   // 192 cols, K=256
__device__ __align__(16) __half2 g_W1f[32*32*4*2];    // 256 cols, K=64
__device__ __align__(16) __half2 g_W2f[ 8*32*16*2];   // 64 cols,  K=256

__device__ float g_bE[192], g_gE[192], g_betaE[192];
__device__ float g_bH[192], g_gH[192], g_betaH[192];

// ---------------- mma / ldmatrix helpers ------------------------------------
__device__ __forceinline__ void mma_f16(float* d, const unsigned int* a,
                                        unsigned int b0, unsigned int b1) {
    asm volatile(
        "mma.sync.aligned.m16n8k16.row.col.f32.f16.f16.f32 "
        "{%0,%1,%2,%3}, {%4,%5,%6,%7}, {%8,%9}, {%0,%1,%2,%3};\n"
        : "+f"(d[0]), "+f"(d[1]), "+f"(d[2]), "+f"(d[3])
        : "r"(a[0]), "r"(a[1]), "r"(a[2]), "r"(a[3]), "r"(b0), "r"(b1));
}
__device__ __forceinline__ void ldsm4(unsigned int* a, const void* p) {
    unsigned int s = (unsigned int)__cvta_generic_to_shared(p);
    asm volatile("ldmatrix.sync.aligned.m8n8.x4.shared.b16 {%0,%1,%2,%3}, [%4];\n"
        : "=r"(a[0]), "=r"(a[1]), "=r"(a[2]), "=r"(a[3]) : "r"(s));
}

// ---------------- K0: pack weights into fragment streams --------------------
__global__ void pack_kernel(
    const float* __restrict__ Wq,  const float* __restrict__ bq,
    const float* __restrict__ Wk,  const float* __restrict__ bk,
    const float* __restrict__ Wv,  const float* __restrict__ bv,
    const float* __restrict__ Wcq, const float* __restrict__ bcq,
    const float* __restrict__ Wck, const float* __restrict__ bck,
    const float* __restrict__ Wcv, const float* __restrict__ bcv,
    const float* __restrict__ gQE, const float* __restrict__ betaQE,
    const float* __restrict__ gKE, const float* __restrict__ betaKE,
    const float* __restrict__ gVE, const float* __restrict__ betaVE,
    const float* __restrict__ gQH, const float* __restrict__ betaQH,
    const float* __restrict__ gKH, const float* __restrict__ betaKH,
    const float* __restrict__ gVH, const float* __restrict__ betaVH,
    const float* __restrict__ W1,  const float* __restrict__ W2)
{
    const int tid0 = blockIdx.x * blockDim.x + threadIdx.x;
    const int stride = gridDim.x * blockDim.x;

    // WE: cols 0..191 over {Wq|Wk|Wv}[64][64], K=64 (4 ksteps)
    for (int idx = tid0; idx < 24*32*4*2; idx += stride) {
        int j = idx & 1, ks = (idx >> 1) & 3, l = (idx >> 3) & 31, nt = idx >> 8;
        int g = l >> 2, t = l & 3;
        int c = nt*8 + g;
        int k = ks*16 + 2*t + j*8;
        int br = c >> 6, cc = c & 63;
        const float* W = (br == 0) ? Wq : (br == 1) ? Wk : Wv;
        g_WEf[idx] = __floats2half2_rn(W[k*64 + cc], W[(k+1)*64 + cc]);
    }
    // WH: cols 0..191 over {Wcq|Wck|Wcv}[256][64], K=256 (16 ksteps)
    for (int idx = tid0; idx < 24*32*16*2; idx += stride) {
        int j = idx & 1, ks = (idx >> 1) & 15, l = (idx >> 5) & 31, nt = idx >> 10;
        int g = l >> 2, t = l & 3;
        int c = nt*8 + g;
        int k = ks*16 + 2*t + j*8;
        int br = c >> 6, cc = c & 63;
        const float* W = (br == 0) ? Wcq : (br == 1) ? Wck : Wcv;
        g_WHf[idx] = __floats2half2_rn(W[k*64 + cc], W[(k+1)*64 + cc]);
    }
    // W1[64][256], K=64
    for (int idx = tid0; idx < 32*32*4*2; idx += stride) {
        int j = idx & 1, ks = (idx >> 1) & 3, l = (idx >> 3) & 31, nt = idx >> 8;
        int g = l >> 2, t = l & 3;
        int c = nt*8 + g;
        int k = ks*16 + 2*t + j*8;
        g_W1f[idx] = __floats2half2_rn(W1[k*256 + c], W1[(k+1)*256 + c]);
    }
    // W2[256][64], K=256
    for (int idx = tid0; idx < 8*32*16*2; idx += stride) {
        int j = idx & 1, ks = (idx >> 1) & 15, l = (idx >> 5) & 31, nt = idx >> 10;
        int g = l >> 2, t = l & 3;
        int c = nt*8 + g;
        int k = ks*16 + 2*t + j*8;
        g_W2f[idx] = __floats2half2_rn(W2[k*64 + c], W2[(k+1)*64 + c]);
    }
    for (int c = tid0; c < 192; c += stride) {
        int br = c >> 6, j = c & 63;
        g_bE[c]    = ((br==0)?bq    :(br==1)?bk    :bv    )[j];
        g_bH[c]    = ((br==0)?bcq   :(br==1)?bck   :bcv   )[j];
        g_gE[c]    = ((br==0)?gQE   :(br==1)?gKE   :gVE   )[j];
        g_betaE[c] = ((br==0)?betaQE:(br==1)?betaKE:betaVE)[j];
        g_gH[c]    = ((br==0)?gQH   :(br==1)?gKH   :gVH   )[j];
        g_betaH[c] = ((br==0)?betaQH:(br==1)?betaKH:betaVH)[j];
    }
}

// ---------------- K1: gated projections via mma -----------------------------
// 16 tokens/block, 256 threads (8 warps). Warp w: 24 cols (3 n8-tiles) at w*24.
#define XR 72
#define HR 264
#define ER 196
__global__ __launch_bounds__(256)
void proj_kernel(const float* __restrict__ state, const float* __restrict__ Hin)
{
    __shared__ __align__(16) __half Xs[16*XR];
    __shared__ __align__(16) __half Hs[16*HR];
    __shared__ __align__(16) float  Ef[16*ER];
    __shared__ __align__(16) float  Hf[16*ER];
    const int tid = threadIdx.x;
    const size_t tok0 = (size_t)blockIdx.x * 16;

    // stage inputs as fp16 (padded strides -> conflict-free ldmatrix)
    {
        int idx = tid * 4;                       // covers 16*64
        int r = idx >> 6, c = idx & 63;
        float4 f = *(const float4*)(state + (tok0 + r)*64 + c);
        *(__half2*)(Xs + r*XR + c)     = __floats2half2_rn(f.x, f.y);
        *(__half2*)(Xs + r*XR + c + 2) = __floats2half2_rn(f.z, f.w);
        #pragma unroll
        for (int it = 0; it < 4; it++) {
            int j2 = (tid + 256*it) * 4;          // covers 16*256
            int rh = j2 >> 8, ch = j2 & 255;
            float4 fh = *(const float4*)(Hin + (tok0 + rh)*256 + ch);
            *(__half2*)(Hs + rh*HR + ch)     = __floats2half2_rn(fh.x, fh.y);
            *(__half2*)(Hs + rh*HR + ch + 2) = __floats2half2_rn(fh.z, fh.w);
        }
    }
    __syncthreads();

    const int w = tid >> 5, l = tid & 31;
    const int g = l >> 2, t = l & 3;
    const int ldrow = (l & 15), ldcol = (l >> 4) * 8;

    // ---- E = state @ WE  (K=64) ----
    float accE[3][4];
    #pragma unroll
    for (int nt = 0; nt < 3; nt++)
        #pragma unroll
        for (int i = 0; i < 4; i++) accE[nt][i] = 0.f;
    #pragma unroll
    for (int ksp = 0; ksp < 2; ksp++) {
        unsigned int a[8];
        ldsm4(a,     Xs + ldrow*XR + ksp*32 + ldcol);
        ldsm4(a + 4, Xs + ldrow*XR + ksp*32 + 16 + ldcol);
        #pragma unroll
        for (int nt = 0; nt < 3; nt++) {
            const uint4 bfrag = *(const uint4*)&g_WEf[(((w*3 + nt)*32 + l)*4 + ksp*2)*2];
            mma_f16(accE[nt], a,     bfrag.x, bfrag.y);
            mma_f16(accE[nt], a + 4, bfrag.z, bfrag.w);
        }
    }
    #pragma unroll
    for (int nt = 0; nt < 3; nt++) {
        int c0 = w*24 + nt*8 + 2*t;
        Ef[g*ER + c0]       = accE[nt][0];
        Ef[g*ER + c0 + 1]   = accE[nt][1];
        Ef[(g+8)*ER + c0]   = accE[nt][2];
        Ef[(g+8)*ER + c0+1] = accE[nt][3];
    }

    // ---- Hh = H @ WH  (K=256) ----
    float accH[3][4];
    #pragma unroll
    for (int nt = 0; nt < 3; nt++)
        #pragma unroll
        for (int i = 0; i < 4; i++) accH[nt][i] = 0.f;
    #pragma unroll
    for (int ksp = 0; ksp < 8; ksp++) {
        unsigned int a[8];
        ldsm4(a,     Hs + ldrow*HR + ksp*32 + ldcol);
        ldsm4(a + 4, Hs + ldrow*HR + ksp*32 + 16 + ldcol);
        #pragma unroll
        for (int nt = 0; nt < 3; nt++) {
            const uint4 bfrag = *(const uint4*)&g_WHf[(((w*3 + nt)*32 + l)*16 + ksp*2)*2];
            mma_f16(accH[nt], a,     bfrag.x, bfrag.y);
            mma_f16(accH[nt], a + 4, bfrag.z, bfrag.w);
        }
    }
    #pragma unroll
    for (int nt = 0; nt < 3; nt++) {
        int c0 = w*24 + nt*8 + 2*t;
        Hf[g*ER + c0]       = accH[nt][0];
        Hf[g*ER + c0 + 1]   = accH[nt][1];
        Hf[(g+8)*ER + c0]   = accH[nt][2];
        Hf[(g+8)*ER + c0+1] = accH[nt][3];
    }
    __syncthreads();

    // ---- LN(E)+LN(H), gate, write q/k/v -------------------------------------
    // 192 workers: (token, branch, 16-col quarter); 4-lane shfl groups.
    if (tid < 192) {
        int tok = tid / 12, sub = tid % 12;
        int br = sub >> 2, qtr = sub & 3;
        int cb = br*64 + qtr*16;
        float e[16], h[16];
        float s1 = 0.f, s2 = 0.f, s3 = 0.f, s4 = 0.f;
        #pragma unroll
        for (int u = 0; u < 16; u++) {
            int c = cb + u;
            float ev = Ef[tok*ER + c] + g_bE[c];
            float hv = Hf[tok*ER + c] + g_bH[c];
            e[u] = ev; h[u] = hv;
            s1 += ev; s2 = fmaf(ev, ev, s2);
            s3 += hv; s4 = fmaf(hv, hv, s4);
        }
        #pragma unroll
        for (int off = 1; off <= 2; off <<= 1) {
            s1 += __shfl_xor_sync(0xffffffffu, s1, off);
            s2 += __shfl_xor_sync(0xffffffffu, s2, off);
            s3 += __shfl_xor_sync(0xffffffffu, s3, off);
            s4 += __shfl_xor_sync(0xffffffffu, s4, off);
        }
        float mE = s1 * (1.f/64.f), mH = s3 * (1.f/64.f);
        float rE = rsqrtf(s2*(1.f/64.f) - mE*mE + 1e-5f);
        float rH = rsqrtf(s4*(1.f/64.f) - mH*mH + 1e-5f);
        float* dst = (br == 0) ? g_q : (br == 1) ? g_k : g_v;
        size_t base = (tok0 + tok)*64 + qtr*16;
        #pragma unroll
        for (int u = 0; u < 16; u++) {
            int c = cb + u;
            dst[base + u] = ((e[u]-mE)*rE*g_gE[c] + g_betaE[c]) *
                            ((h[u]-mH)*rH*g_gH[c] + g_betaH[c]);
        }
    }
}

// ---------------- K2: attention + residual -> Z1 (fp32) ---------------------
#define ACH 150
__global__ __launch_bounds__(320, 2)
void attn_kernel(const float* __restrict__ state)
{
    __shared__ __align__(16) float4 Ks[ACH*8];
    __shared__ __align__(16) float4 Vs[ACH*8];
    const int tid = threadIdx.x;
    const int b = blockIdx.x >> 1, h = blockIdx.x & 1;
    const size_t base = (size_t)b * S_ * 64 + h * 32;

    float4 qv[8];
    float acc[32];
    float l = 0.f;
    const bool active = (tid < S_);
    if (active) {
        const float4* qp = (const float4*)(g_q + base + (size_t)tid*64);
        const float sc = 0.17677669529663687f;   // 1/sqrt(32)
        #pragma unroll
        for (int j = 0; j < 8; j++) {
            float4 v = qp[j];
            v.x *= sc; v.y *= sc; v.z *= sc; v.w *= sc;
            qv[j] = v;
        }
        #pragma unroll
        for (int d = 0; d < 32; d++) acc[d] = 0.f;
    }

    for (int c0 = 0; c0 < S_; c0 += ACH) {
        __syncthreads();
        for (int idx = tid; idx < ACH*8; idx += 320) {
            int kk = idx >> 3, j = idx & 7;
            size_t g = base + (size_t)(c0 + kk)*64;
            Ks[idx] = ((const float4*)(g_k + g))[j];
            Vs[idx] = ((const float4*)(g_v + g))[j];
        }
        __syncthreads();
        if (active) {
            for (int kk = 0; kk < ACH; kk++) {
                const float4* kr = &Ks[kk*8];
                float dx = 0.f, dy = 0.f, dz = 0.f, dw = 0.f;
                #pragma unroll
                for (int j = 0; j < 8; j++) {
                    float4 k4 = kr[j];
                    dx = fmaf(qv[j].x, k4.x, dx);
                    dy = fmaf(qv[j].y, k4.y, dy);
                    dz = fmaf(qv[j].z, k4.z, dz);
                    dw = fmaf(qv[j].w, k4.w, dw);
                }
                float p = __expf((dx + dy) + (dz + dw));
                l += p;
                const float4* vr = &Vs[kk*8];
                #pragma unroll
                for (int j = 0; j < 8; j++) {
                    float4 v4 = vr[j];
                    acc[4*j+0] = fmaf(p, v4.x, acc[4*j+0]);
                    acc[4*j+1] = fmaf(p, v4.y, acc[4*j+1]);
                    acc[4*j+2] = fmaf(p, v4.z, acc[4*j+2]);
                    acc[4*j+3] = fmaf(p, v4.w, acc[4*j+3]);
                }
            }
        }
    }

    if (active) {
        float inv = 1.0f / l;
        const float4* sp = (const float4*)(state + base + (size_t)tid*64);
        float4* zp = (float4*)(g_z1 + base + (size_t)tid*64);
        #pragma unroll
        for (int j = 0; j < 8; j++) {
            float4 sv = sp[j]; float4 o;
            o.x = fmaf(acc[4*j+0], inv, sv.x);
            o.y = fmaf(acc[4*j+1], inv, sv.y);
            o.z = fmaf(acc[4*j+2], inv, sv.z);
            o.w = fmaf(acc[4*j+3], inv, sv.w);
            zp[j] = o;
        }
    }
}

// ---------------- K3: LN -> FFN(gelu) -> +Z1 via mma ------------------------
// 32 tokens/block, 256 threads (8 warps).
#define ZR  72
#define H3R 264
#define Z1R 68
__global__ __launch_bounds__(256)
void ffn_kernel(const float* __restrict__ b1, const float* __restrict__ b2,
                const float* __restrict__ g1, const float* __restrict__ beta1,
                float* __restrict__ out)
{
    __shared__ __align__(16) __half Z2s[32*ZR];
    __shared__ __align__(16) __half H3s[32*H3R];
    __shared__ __align__(16) float  Z1s[32*Z1R];
    const int tid = threadIdx.x;
    const size_t tok0 = (size_t)blockIdx.x * 32;

    // ---- Phase 1: LN(z1) -> fp16, stash z1 fp32 -----------------------------
    {
        int tk = tid >> 3, sg = tid & 7;         // 8 floats per thread
        const float* src = g_z1 + (tok0 + tk)*64 + sg*8;
        float4 f0 = *(const float4*)src;
        float4 f1 = *(const float4*)(src + 4);
        float v[8] = {f0.x, f0.y, f0.z, f0.w, f1.x, f1.y, f1.z, f1.w};
        float s1 = 0.f, s2 = 0.f;
        #pragma unroll
        for (int u = 0; u < 8; u++) { s1 += v[u]; s2 = fmaf(v[u], v[u], s2); }
        #pragma unroll
        for (int off = 1; off <= 4; off <<= 1) {
            s1 += __shfl_xor_sync(0xffffffffu, s1, off);
            s2 += __shfl_xor_sync(0xffffffffu, s2, off);
        }
        float m = s1 * (1.f/64.f);
        float r = rsqrtf(s2*(1.f/64.f) - m*m + 1e-5f);
        *(float4*)(Z1s + tk*Z1R + sg*8)     = f0;
        *(float4*)(Z1s + tk*Z1R + sg*8 + 4) = f1;
        #pragma unroll
        for (int u = 0; u < 8; u += 2) {
            int c = sg*8 + u;
            float a0 = (v[u]   - m)*r*g1[c]   + beta1[c];
            float a1 = (v[u+1] - m)*r*g1[c+1] + beta1[c+1];
            *(__half2*)(Z2s + tk*ZR + c) = __floats2half2_rn(a0, a1);
        }
    }
    __syncthreads();

    const int w = tid >> 5, l = tid & 31;
    const int g = l >> 2, t = l & 3;
    const int ldrow = (l & 15), ldcol = (l >> 4) * 8;
    const int mt = w & 1;

    // ---- GEMM1: [32,64]@W1 -> [32,256], exact GELU --------------------------
    {
        const int cq = w >> 1;                    // col quarter (64 cols)
        float acc1[8][4];
        #pragma unroll
        for (int nt = 0; nt < 8; nt++)
            #pragma unroll
            for (int i = 0; i < 4; i++) acc1[nt][i] = 0.f;
        #pragma unroll
        for (int ksp = 0; ksp < 2; ksp++) {
            unsigned int a[8];
            ldsm4(a,     Z2s + (mt*16 + ldrow)*ZR + ksp*32 + ldcol);
            ldsm4(a + 4, Z2s + (mt*16 + ldrow)*ZR + ksp*32 + 16 + ldcol);
            #pragma unroll
            for (int nt = 0; nt < 8; nt++) {
                const uint4 bfrag = *(const uint4*)&g_W1f[(((cq*8 + nt)*32 + l)*4 + ksp*2)*2];
                mma_f16(acc1[nt], a,     bfrag.x, bfrag.y);
                mma_f16(acc1[nt], a + 4, bfrag.z, bfrag.w);
            }
        }
        #pragma unroll
        for (int nt = 0; nt < 8; nt++) {
            int c0 = cq*64 + nt*8 + 2*t;
            float bb0 = b1[c0], bb1 = b1[c0 + 1];
            float x0 = acc1[nt][0] + bb0, x1 = acc1[nt][1] + bb1;
            float x2 = acc1[nt][2] + bb0, x3 = acc1[nt][3] + bb1;
            x0 = 0.5f*x0*(1.f + erff(x0*0.70710678118654752f));
            x1 = 0.5f*x1*(1.f + erff(x1*0.70710678118654752f));
            x2 = 0.5f*x2*(1.f + erff(x2*0.70710678118654752f));
            x3 = 0.5f*x3*(1.f + erff(x3*0.70710678118654752f));
            *(__half2*)(H3s + (mt*16 + g)*H3R + c0)     = __floats2half2_rn(x0, x1);
            *(__half2*)(H3s + (mt*16 + g + 8)*H3R + c0) = __floats2half2_rn(x2, x3);
        }
    }
    __syncthreads();

    // ---- GEMM2: [32,256]@W2 -> [32,64], + b2 + residual ---------------------
    {
        const int np = w >> 1;                    // 16-col slice
        float acc2[2][4];
        #pragma unroll
        for (int nt = 0; nt < 2; nt++)
            #pragma unroll
            for (int i = 0; i < 4; i++) acc2[nt][i] = 0.f;
        #pragma unroll
        for (int ksp = 0; ksp < 8; ksp++) {
            unsigned int a[8];
            ldsm4(a,     H3s + (mt*16 + ldrow)*H3R + ksp*32 + ldcol);
            ldsm4(a + 4, H3s + (mt*16 + ldrow)*H3R + ksp*32 + 16 + ldcol);
            #pragma unroll
            for (int nt = 0; nt < 2; nt++) {
                const uint4 bfrag = *(const uint4*)&g_W2f[(((np*2 + nt)*32 + l)*16 + ksp*2)*2];
                mma_f16(acc2[nt], a,     bfrag.x, bfrag.y);
                mma_f16(acc2[nt], a + 4, bfrag.z, bfrag.w);
            }
        }
        #pragma unroll
        for (int nt = 0; nt < 2; nt++) {
            int c0 = np*16 + nt*8 + 2*t;
            int r0 = mt*16 + g;
            float bb0 = b2[c0], bb1 = b2[c0 + 1];
            out[(tok0 + r0)*64 + c0]       = acc2[nt][0] + bb0 + Z1s[r0*Z1R + c0];
            out[(tok0 + r0)*64 + c0 + 1]   = acc2[nt][1] + bb1 + Z1s[r0*Z1R + c0 + 1];
            out[(tok0 + r0 + 8)*64 + c0]   = acc2[nt][2] + bb0 + Z1s[(r0+8)*Z1R + c0];
            out[(tok0 + r0 + 8)*64 + c0+1] = acc2[nt][3] + bb1 + Z1s[(r0+8)*Z1R + c0 + 1];
        }
    }
}

// ---------------- launcher --------------------------------------------------
extern "C" void kernel_launch(void* const* d_in, const int* in_sizes, int n_in,
                              void* d_out, int out_size)
{
    const float* state  = (const float*)d_in[0];
    const float* H      = (const float*)d_in[1];
    const float* Wq     = (const float*)d_in[2];
    const float* bq     = (const float*)d_in[3];
    const float* Wk     = (const float*)d_in[4];
    const float* bk     = (const float*)d_in[5];
    const float* Wv     = (const float*)d_in[6];
    const float* bv     = (const float*)d_in[7];
    const float* Wcq    = (const float*)d_in[8];
    const float* bcq    = (const float*)d_in[9];
    const float* Wck    = (const float*)d_in[10];
    const float* bck    = (const float*)d_in[11];
    const float* Wcv    = (const float*)d_in[12];
    const float* bcv    = (const float*)d_in[13];
    const float* gQE    = (const float*)d_in[14];
    const float* betaQE = (const float*)d_in[15];
    const float* gKE    = (const float*)d_in[16];
    const float* betaKE = (const float*)d_in[17];
    const float* gVE    = (const float*)d_in[18];
    const float* betaVE = (const float*)d_in[19];
    const float* gQH    = (const float*)d_in[20];
    const float* betaQH = (const float*)d_in[21];
    const float* gKH    = (const float*)d_in[22];
    const float* betaKH = (const float*)d_in[23];
    const float* gVH    = (const float*)d_in[24];
    const float* betaVH = (const float*)d_in[25];
    const float* W1     = (const float*)d_in[26];
    const float* b1     = (const float*)d_in[27];
    const float* W2     = (const float*)d_in[28];
    const float* b2     = (const float*)d_in[29];
    const float* g1     = (const float*)d_in[30];
    const float* beta1  = (const float*)d_in[31];
    float* out = (float*)d_out;

    pack_kernel<<<192, 256>>>(Wq, bq, Wk, bk, Wv, bv,
                              Wcq, bcq, Wck, bck, Wcv, bcv,
                              gQE, betaQE, gKE, betaKE, gVE, betaVE,
                              gQH, betaQH, gKH, betaKH, gVH, betaVH,
                              W1, W2);
    proj_kernel<<<NTOK/16, 256>>>(state, H);
    attn_kernel<<<B_*2, 320>>>(state);
    ffn_kernel<<<NTOK/32, 256>>>(b1, b2, g1, beta1, out);
}